// round 7
// baseline (speedup 1.0000x reference)
#include <cuda_runtime.h>
#include <cuda_fp16.h>
#include <math.h>

// Problem constants
#define BATCH    64
#define IN_CAPS  2048
#define IN_DIM   16
#define NUM_CAPS 32
#define OUT_DIM  16
#define JD       512            // NUM_CAPS * OUT_DIM
#define NIC      32             // i-chunks per batch in iter kernel
#define IC       (IN_CAPS/NIC)  // 64 i's per block

// Scratch (device globals; allocation-free per harness rules)
__device__ __align__(16) __half g_uhat[(size_t)BATCH * IN_CAPS * JD];  // 128 MB, [b][i][j*16+d]
__device__ float g_spart[(size_t)BATCH * NIC * JD];  // 4 MB, d-major [b][ic][d*32+j]
__device__ float g_out0[(size_t)BATCH * JD];         // d-major [b][d*32+j]
__device__ float g_out1[(size_t)BATCH * JD];

// ---- packed f32x2 helpers (sm_103a) ---------------------------------------
static __device__ __forceinline__ unsigned long long pack2(float lo, float hi) {
    unsigned long long r;
    asm("mov.b64 %0, {%1, %2};" : "=l"(r) : "f"(lo), "f"(hi));
    return r;
}
#define FMA2(d, a, b, c) asm("fma.rn.f32x2 %0, %1, %2, %3;" : "=l"(d) : "l"(a), "l"(b), "l"(c))
#define MUL2(d, a, b)    asm("mul.rn.f32x2 %0, %1, %2;"     : "=l"(d) : "l"(a), "l"(b))

// ---------------------------------------------------------------------------
// K1: u_hat[b,i,jd] = sum_k W[i,jd,k] * x[b,i,k]  -> fp16
// One block per i, 512 threads. Thread t: pr = t&255 owns the jd-pair
// (2pr, 2pr+1); hb = t>>8 selects a batch half (32 b's). W packed as
// (W[jd0,k], W[jd1,k]) f32x2 pairs in regs; x staged in smem as (x,x) pairs
// (warp-broadcast LDS). Each b: 16 FMA2 -> both d's; store ONE half2
// (warp writes 128B contiguous).
// ---------------------------------------------------------------------------
__global__ __launch_bounds__(512) void uhat_kernel(
    const float* __restrict__ x, const float* __restrict__ W)
{
    const int i  = blockIdx.x;
    const int t  = threadIdx.x;         // 0..511
    const int pr = t & 255;             // jd pair index
    const int hb = t >> 8;              // batch half: 0 or 1
    const int jd0 = 2 * pr;

    __shared__ unsigned long long xp[BATCH][16];   // (x,x) pairs, 8 KB

    {   // load x: two (b,k) entries per thread, 64B-coalesced per warp
        int b = t >> 4, k = t & 15;
        float v0 = x[((size_t)b        * IN_CAPS + i) * IN_DIM + k];
        float v1 = x[((size_t)(b + 32) * IN_CAPS + i) * IN_DIM + k];
        xp[b][k]      = pack2(v0, v0);
        xp[b + 32][k] = pack2(v1, v1);
    }

    // W rows jd0, jd0+1 -> packed pairs
    const float4* W0 = (const float4*)(W + ((size_t)i * JD + jd0) * IN_DIM);
    const float4* W1 = (const float4*)(W + ((size_t)i * JD + jd0 + 1) * IN_DIM);
    unsigned long long wp[16];
    #pragma unroll
    for (int q = 0; q < 4; q++) {
        float4 a = W0[q], b = W1[q];
        wp[4 * q + 0] = pack2(a.x, b.x);
        wp[4 * q + 1] = pack2(a.y, b.y);
        wp[4 * q + 2] = pack2(a.z, b.z);
        wp[4 * q + 3] = pack2(a.w, b.w);
    }

    __syncthreads();

    __half2* out = (__half2*)(g_uhat + ((size_t)(hb * 32) * IN_CAPS + i) * JD + jd0);
    #pragma unroll 4
    for (int bb = 0; bb < 32; bb++) {
        const ulonglong2* ap = (const ulonglong2*)xp[hb * 32 + bb];
        ulonglong2 a0 = ap[0], a1 = ap[1], a2 = ap[2], a3 = ap[3];
        ulonglong2 a4 = ap[4], a5 = ap[5], a6 = ap[6], a7 = ap[7];
        unsigned long long acc;
        MUL2(acc, wp[0],  a0.x);
        FMA2(acc, wp[1],  a0.y, acc);
        FMA2(acc, wp[2],  a1.x, acc);
        FMA2(acc, wp[3],  a1.y, acc);
        FMA2(acc, wp[4],  a2.x, acc);
        FMA2(acc, wp[5],  a2.y, acc);
        FMA2(acc, wp[6],  a3.x, acc);
        FMA2(acc, wp[7],  a3.y, acc);
        FMA2(acc, wp[8],  a4.x, acc);
        FMA2(acc, wp[9],  a4.y, acc);
        FMA2(acc, wp[10], a5.x, acc);
        FMA2(acc, wp[11], a5.y, acc);
        FMA2(acc, wp[12], a6.x, acc);
        FMA2(acc, wp[13], a6.y, acc);
        FMA2(acc, wp[14], a7.x, acc);
        FMA2(acc, wp[15], a7.y, acc);
        float lo, hi;
        asm("mov.b64 {%0, %1}, %2;" : "=f"(lo), "=f"(hi) : "l"(acc));
        out[(size_t)bb * IN_CAPS * (JD / 2)] = __floats2half2_rn(lo, hi);
    }
}

// ---------------------------------------------------------------------------
// Fused routing iteration. Lane = j; lane loads u_hat[b,i,lane,0:15] (32B).
// Agreement dot in half2 (8 HFMA2); softmax over j WITHOUT max subtraction
// (exact: shift-invariant, |a| <= ~40 so exp is finite) -> single 5-step
// butterfly per i. Two i's in flight per step.
//   iter1 logits = <u, out0>;  iter2 logits = <u, out0 + out1>.
// ---------------------------------------------------------------------------
__global__ __launch_bounds__(256, 4) void iter_kernel(int iter)
{
    const int b    = blockIdx.y;
    const int ic   = blockIdx.x;
    const int t    = threadIdx.x;
    const int w    = t >> 5;
    const int lane = t & 31;            // = j
    const int i0   = ic * IC;

    __half2 vout2[8];
    if (iter > 0) {
        #pragma unroll
        for (int d2 = 0; d2 < 8; d2++) {
            float f0 = g_out0[(size_t)b * JD + (2 * d2)     * 32 + lane];
            float f1 = g_out0[(size_t)b * JD + (2 * d2 + 1) * 32 + lane];
            if (iter == 2) {
                f0 += g_out1[(size_t)b * JD + (2 * d2)     * 32 + lane];
                f1 += g_out1[(size_t)b * JD + (2 * d2 + 1) * 32 + lane];
            }
            vout2[d2] = __floats2half2_rn(f0, f1);
        }
    }

    float acc[16];
    #pragma unroll
    for (int d = 0; d < 16; d++) acc[d] = 0.f;

    const __half* uhbase = g_uhat + ((size_t)b * IN_CAPS + i0) * JD + lane * 16;

    #pragma unroll
    for (int step = 0; step < 4; step++) {
        const int iiA = w + step * 16;
        const int iiB = iiA + 8;
        const uint4* pA = (const uint4*)(uhbase + (size_t)iiA * JD);
        const uint4* pB = (const uint4*)(uhbase + (size_t)iiB * JD);
        uint4 ra0 = pA[0], ra1 = pA[1];     // i = iiA : d 0..7, 8..15
        uint4 rb0 = pB[0], rb1 = pB[1];     // i = iiB

        if (iter == 0) {
            #pragma unroll
            for (int half_sel = 0; half_sel < 2; half_sel++) {
                const __half2* v2 = (const __half2*)(half_sel ? &rb0 : &ra0);
                const __half2* v3 = (const __half2*)(half_sel ? &rb1 : &ra1);
                #pragma unroll
                for (int d2 = 0; d2 < 4; d2++) {
                    float2 f = __half22float2(v2[d2]);
                    acc[2 * d2]     += f.x;
                    acc[2 * d2 + 1] += f.y;
                    float2 g = __half22float2(v3[d2]);
                    acc[8 + 2 * d2]     += g.x;
                    acc[8 + 2 * d2 + 1] += g.y;
                }
            }
        } else {
            // Agreement dots for both i's (independent chains, ILP)
            __half2 hA = __hmul2(((const __half2*)&ra0)[0], vout2[0]);
            __half2 hB = __hmul2(((const __half2*)&rb0)[0], vout2[0]);
            #pragma unroll
            for (int d2 = 1; d2 < 4; d2++) {
                hA = __hfma2(((const __half2*)&ra0)[d2], vout2[d2], hA);
                hB = __hfma2(((const __half2*)&rb0)[d2], vout2[d2], hB);
            }
            #pragma unroll
            for (int d2 = 0; d2 < 4; d2++) {
                hA = __hfma2(((const __half2*)&ra1)[d2], vout2[4 + d2], hA);
                hB = __hfma2(((const __half2*)&rb1)[d2], vout2[4 + d2], hB);
            }
            float eA = __expf(__low2float(hA) + __high2float(hA));
            float eB = __expf(__low2float(hB) + __high2float(hB));

            float sA = eA, sB = eB;   // interleaved butterflies (no max pass)
            #pragma unroll
            for (int o = 16; o; o >>= 1) {
                sA += __shfl_xor_sync(0xffffffffu, sA, o);
                sB += __shfl_xor_sync(0xffffffffu, sB, o);
            }
            float cA = eA / sA;
            float cB = eB / sB;

            #pragma unroll
            for (int d2 = 0; d2 < 4; d2++) {
                float2 f = __half22float2(((const __half2*)&ra0)[d2]);
                acc[2 * d2]     = fmaf(cA, f.x, acc[2 * d2]);
                acc[2 * d2 + 1] = fmaf(cA, f.y, acc[2 * d2 + 1]);
                float2 g = __half22float2(((const __half2*)&ra1)[d2]);
                acc[8 + 2 * d2]     = fmaf(cA, g.x, acc[8 + 2 * d2]);
                acc[8 + 2 * d2 + 1] = fmaf(cA, g.y, acc[8 + 2 * d2 + 1]);
            }
            #pragma unroll
            for (int d2 = 0; d2 < 4; d2++) {
                float2 f = __half22float2(((const __half2*)&rb0)[d2]);
                acc[2 * d2]     = fmaf(cB, f.x, acc[2 * d2]);
                acc[2 * d2 + 1] = fmaf(cB, f.y, acc[2 * d2 + 1]);
                float2 g = __half22float2(((const __half2*)&rb1)[d2]);
                acc[8 + 2 * d2]     = fmaf(cB, g.x, acc[8 + 2 * d2]);
                acc[8 + 2 * d2 + 1] = fmaf(cB, g.y, acc[8 + 2 * d2 + 1]);
            }
        }
    }

    if (iter == 0) {
        #pragma unroll
        for (int d = 0; d < 16; d++) acc[d] *= (1.0f / NUM_CAPS);
    }

    // Cross-warp reduce (d-major in smem: conflict-free)
    __shared__ float red[8][JD];
    #pragma unroll
    for (int d = 0; d < 16; d++) red[w][d * 32 + lane] = acc[d];
    __syncthreads();

    float s1 = 0.f, s2 = 0.f;
    #pragma unroll
    for (int ww = 0; ww < 8; ww++) {
        s1 += red[ww][t];
        s2 += red[ww][t + 256];
    }
    float* sp = g_spart + ((size_t)b * NIC + ic) * JD;
    sp[t]       = s1;
    sp[t + 256] = s2;
}

// ---------------------------------------------------------------------------
// Reduce partials over NIC chunks + squash. d-major positions: t = d*32 + j.
// which: 0 -> g_out0, 1 -> g_out1, 2 -> dout (permuted to [b][j][d]).
// ---------------------------------------------------------------------------
__global__ __launch_bounds__(512) void squash_kernel(int which, float* __restrict__ dout)
{
    const int b = blockIdx.x;
    const int t = threadIdx.x;

    const float* sp = g_spart + (size_t)b * NIC * JD + t;
    float s = 0.f;
    #pragma unroll
    for (int p = 0; p < NIC; p++) s += sp[(size_t)p * JD];

    __shared__ float s2s[NUM_CAPS];
    if (t < NUM_CAPS) s2s[t] = 0.f;
    __syncthreads();
    atomicAdd(&s2s[t & 31], s * s);
    __syncthreads();

    float s2 = s2s[t & 31];
    float scale = s2 / ((1.0f + s2) * sqrtf(s2 + 1e-7f));
    float v = s * scale;

    if (which == 2)      dout[(size_t)b * JD + (t & 31) * 16 + (t >> 5)] = v;
    else if (which == 0) g_out0[(size_t)b * JD + t] = v;
    else                 g_out1[(size_t)b * JD + t] = v;
}

// ---------------------------------------------------------------------------
extern "C" void kernel_launch(void* const* d_in, const int* in_sizes, int n_in,
                              void* d_out, int out_size)
{
    const float* x = (const float*)d_in[0];
    const float* W = (const float*)d_in[1];
    if (in_sizes[0] == (int)((size_t)IN_CAPS * NUM_CAPS * IN_DIM * OUT_DIM)) {
        const float* tmp = x; x = W; W = tmp;
    }
    float* out = (float*)d_out;

    dim3 ig(NIC, BATCH);

    uhat_kernel<<<IN_CAPS, 512>>>(x, W);

    iter_kernel<<<ig, 256>>>(0);
    squash_kernel<<<BATCH, 512>>>(0, out);   // -> g_out0

    iter_kernel<<<ig, 256>>>(1);
    squash_kernel<<<BATCH, 512>>>(1, out);   // -> g_out1

    iter_kernel<<<ig, 256>>>(2);
    squash_kernel<<<BATCH, 512>>>(2, out);   // -> dout
}